// round 16
// baseline (speedup 1.0000x reference)
#include <cuda_runtime.h>
#include <cuda_bf16.h>
#include <cstdint>
#include <math.h>

// ---------------------------------------------------------------------------
// Problem constants
//   B=2, H=W=256, C=192, HEADS=6, HEAD_DIM=32, WS=8, PW=4, HIDDEN=768
//   NTOK = B*H*W = 131072 tokens
// ---------------------------------------------------------------------------
#define NTOK   131072
#define QKVLD  288      // 192 (q) + 96 (kv) per token, bf16
#define HID    768
#define ATT_SCALE 0.17677669529663688f   // 32^-0.5

// Scratch (static device allocations — no cudaMalloc allowed)
__device__ __align__(16) __nv_bfloat16 g_xn  [(size_t)NTOK * 192]; // LN out
__device__ __align__(16) __nv_bfloat16 g_qkvb[(size_t)NTOK * QKVLD];
__device__ __align__(16) __nv_bfloat16 g_aw  [(size_t)NTOK * 192]; // attn out
__device__ __align__(16) float         g_x2  [(size_t)NTOK * 192]; // resid
__device__ __align__(16) __nv_bfloat16 g_h1  [(size_t)NTOK * HID]; // gelu(fc1)
__device__ __align__(16) __nv_bfloat16 g_h   [(size_t)NTOK * HID]; // ffn hidden
// bf16 weights: wqkv (192x288) | wproj | w1f | w2f
#define WB_WQKV  0
#define WB_WPROJ 55296
#define WB_W1F   92160
#define WB_W2F   239616
__device__ __align__(16) __nv_bfloat16 g_wb[387072];
__device__ __align__(16) float g_bqkv[288];

__device__ __forceinline__ float gelu_f(float v) {
    return 0.5f * v * (1.0f + erff(v * 0.70710678118654752440f));
}

// ---------------------------------------------------------------------------
// Weight/bias prep: concat wq|wkv into 192x288 + convert all weights to bf16
// ---------------------------------------------------------------------------
__global__ __launch_bounds__(256) void prep_kernel(
    const float* __restrict__ wq, const float* __restrict__ wkv,
    const float* __restrict__ wproj, const float* __restrict__ w1f,
    const float* __restrict__ w2f, __nv_bfloat16* __restrict__ wb,
    const float* __restrict__ bq, const float* __restrict__ bkv,
    float* __restrict__ bqkv)
{
    int i = blockIdx.x * 256 + threadIdx.x;
    if (i < 288) bqkv[i] = (i < 192) ? bq[i] : bkv[i - 192];
    if (i >= 387072) return;
    float v;
    if (i < 55296) {
        int row = i / 288, col = i - row * 288;
        v = (col < 192) ? wq[row * 192 + col] : wkv[row * 96 + col - 192];
    } else if (i < 92160) {
        v = wproj[i - 55296];
    } else if (i < 239616) {
        v = w1f[i - 92160];
    } else {
        v = w2f[i - 239616];
    }
    wb[i] = __float2bfloat16(v);
}

// ---------------------------------------------------------------------------
// LayerNorm: one warp per 192-wide row, bf16 output
// ---------------------------------------------------------------------------
__global__ __launch_bounds__(256) void ln_kernel(
    const float* __restrict__ x, const float* __restrict__ g,
    const float* __restrict__ b, __nv_bfloat16* __restrict__ out)
{
    int row  = blockIdx.x * 8 + (threadIdx.x >> 5);
    int lane = threadIdx.x & 31;
    const float* xp = x + (size_t)row * 192;
    float v[6]; float s = 0.f;
#pragma unroll
    for (int i = 0; i < 6; i++) { v[i] = xp[lane + 32*i]; s += v[i]; }
#pragma unroll
    for (int o = 16; o > 0; o >>= 1) s += __shfl_xor_sync(0xffffffffu, s, o);
    float mu = s * (1.f/192.f);
    float var = 0.f;
#pragma unroll
    for (int i = 0; i < 6; i++) { float d = v[i] - mu; var += d*d; }
#pragma unroll
    for (int o = 16; o > 0; o >>= 1) var += __shfl_xor_sync(0xffffffffu, var, o);
    float inv = rsqrtf(var * (1.f/192.f) + 1e-5f);
    __nv_bfloat16* op = out + (size_t)row * 192;
#pragma unroll
    for (int i = 0; i < 6; i++) {
        int c = lane + 32*i;
        op[c] = __float2bfloat16((v[i] - mu) * inv * g[c] + b[c]);
    }
}

// ---------------------------------------------------------------------------
// bf16 tensor-core GEMM — occupancy-optimized small CTA.
// BM=64, BN=64, BK=32; 128 threads = 4 warps (2m x 2n), warp tile 32x32.
// Static smem 28.5 KB -> ~7 CTAs/SM (28 warps) for latency hiding.
// 3-stage cp.async pipeline, mainloop unrolled modulo 3 (compile-time slots),
// t+2 loads issued before the wait. REQUIRES K % 96 == 0 (K = 192/768 here).
//   C[m,n] = act( A[m,:] @ W[:,n] + bias[n] ) (+ res[m,n])
// ---------------------------------------------------------------------------
__device__ __forceinline__ void cp16(uint32_t dst, const void* src, bool ok) {
    int sz = ok ? 16 : 0;
    asm volatile("cp.async.cg.shared.global [%0], [%1], 16, %2;\n"
                 :: "r"(dst), "l"(src), "r"(sz));
}
__device__ __forceinline__ void ldmx4(unsigned r[4], uint32_t addr) {
    asm volatile("ldmatrix.sync.aligned.m8n8.x4.shared.b16 {%0,%1,%2,%3}, [%4];"
                 : "=r"(r[0]), "=r"(r[1]), "=r"(r[2]), "=r"(r[3]) : "r"(addr));
}
__device__ __forceinline__ void ldmx4t(unsigned r[4], uint32_t addr) {
    asm volatile("ldmatrix.sync.aligned.m8n8.x4.trans.shared.b16 {%0,%1,%2,%3}, [%4];"
                 : "=r"(r[0]), "=r"(r[1]), "=r"(r[2]), "=r"(r[3]) : "r"(addr));
}
__device__ __forceinline__ void mma_bf16(float c[4], const unsigned a[4],
                                         unsigned b0, unsigned b1) {
    asm volatile(
        "mma.sync.aligned.m16n8k16.row.col.f32.bf16.bf16.f32 "
        "{%0,%1,%2,%3}, {%4,%5,%6,%7}, {%8,%9}, {%0,%1,%2,%3};"
        : "+f"(c[0]), "+f"(c[1]), "+f"(c[2]), "+f"(c[3])
        : "r"(a[0]), "r"(a[1]), "r"(a[2]), "r"(a[3]), "r"(b0), "r"(b1));
}

#define SA 40
#define SB 72

__global__ __launch_bounds__(128) void gemm_bf16_kernel(
    const __nv_bfloat16* __restrict__ A, int lda,
    const __nv_bfloat16* __restrict__ W, int ldw,
    const float* __restrict__ bias,
    void* __restrict__ Cc, int ldc,
    int N, int K,
    const float* __restrict__ res, int act, int out_bf16)
{
    __shared__ __align__(16) __nv_bfloat16 As[3][64 * SA];
    __shared__ __align__(16) __nv_bfloat16 Bs[3][32 * SB];
    int tid  = threadIdx.x;
    int lane = tid & 31;
    int warp = tid >> 5;
    int m0 = blockIdx.y * 64;
    int n0 = blockIdx.x * 64;
    int wm0 = (warp >> 1) * 32;
    int wn0 = (warp & 1) * 32;
    int g  = lane >> 2, cq = lane & 3;
    int ln15 = lane & 15, hi8 = (lane >> 4) << 3;

    uint32_t sAb[3], sBb[3];
#pragma unroll
    for (int s = 0; s < 3; s++) {
        sAb[s] = (uint32_t)__cvta_generic_to_shared(&As[s][0]);
        sBb[s] = (uint32_t)__cvta_generic_to_shared(&Bs[s][0]);
    }

    float acc[2][4][4];
#pragma unroll
    for (int mt = 0; mt < 2; mt++)
#pragma unroll
        for (int nt = 0; nt < 4; nt++)
#pragma unroll
            for (int r = 0; r < 4; r++) acc[mt][nt][r] = 0.f;

    // Loaders: A 64x32 = 256 16B-chunks, B 32x64 = 256 chunks; 2 each/thread.
    int a_r0 = tid >> 2, a_c = (tid & 3) << 3;        // rows r0, r0+32
    int b_kr = tid >> 3, b_nq = (tid & 7) << 3;       // rows kr, kr+16
    bool b_ok = (n0 + b_nq + 8) <= N;

    int T = K >> 5;   // divisible by 3 for all uses
#define LOAD_TILE(slot, t_)                                                    \
    do {                                                                       \
        int kt_ = (t_) << 5;                                                   \
        cp16(sAb[slot] + (a_r0 * SA + a_c) * 2,                                \
             A + (size_t)(m0 + a_r0) * lda + kt_ + a_c, true);                 \
        cp16(sAb[slot] + ((a_r0 + 32) * SA + a_c) * 2,                         \
             A + (size_t)(m0 + a_r0 + 32) * lda + kt_ + a_c, true);            \
        cp16(sBb[slot] + (b_kr * SB + b_nq) * 2,                               \
             b_ok ? (const void*)(W + (size_t)(kt_ + b_kr) * ldw + n0 + b_nq)  \
                  : (const void*)W, b_ok);                                     \
        cp16(sBb[slot] + ((b_kr + 16) * SB + b_nq) * 2,                        \
             b_ok ? (const void*)(W + (size_t)(kt_ + b_kr + 16) * ldw + n0 + b_nq) \
                  : (const void*)W, b_ok);                                     \
        asm volatile("cp.async.commit_group;\n");                              \
    } while (0)

#define COMPUTE(slot)                                                          \
    do {                                                                       \
        uint32_t ab = sAb[slot], bb = sBb[slot];                               \
        _Pragma("unroll")                                                      \
        for (int kb = 0; kb < 32; kb += 16) {                                  \
            unsigned af[2][4], bf[2][4];                                       \
            _Pragma("unroll")                                                  \
            for (int mt = 0; mt < 2; mt++)                                     \
                ldmx4(af[mt], ab + ((wm0 + mt*16 + ln15) * SA + kb + hi8) * 2);\
            _Pragma("unroll")                                                  \
            for (int np = 0; np < 2; np++)                                     \
                ldmx4t(bf[np], bb + ((kb + ln15) * SB + wn0 + np*16 + hi8) * 2);\
            _Pragma("unroll")                                                  \
            for (int mt = 0; mt < 2; mt++)                                     \
                _Pragma("unroll")                                              \
                for (int nt = 0; nt < 4; nt++)                                 \
                    mma_bf16(acc[mt][nt], af[mt],                              \
                             bf[nt >> 1][(nt & 1) * 2],                        \
                             bf[nt >> 1][(nt & 1) * 2 + 1]);                   \
        }                                                                      \
    } while (0)

#define STEP(slot, nslot, t_)                                                  \
    do {                                                                       \
        __syncthreads();                                                       \
        if ((t_) + 2 < T) {                                                    \
            LOAD_TILE(nslot, (t_) + 2);                                        \
            asm volatile("cp.async.wait_group 2;\n");                          \
        } else if ((t_) + 1 < T) {                                             \
            asm volatile("cp.async.wait_group 1;\n");                          \
        } else {                                                               \
            asm volatile("cp.async.wait_group 0;\n");                          \
        }                                                                      \
        __syncthreads();                                                       \
        COMPUTE(slot);                                                         \
    } while (0)

    LOAD_TILE(0, 0);
    LOAD_TILE(1, 1);
    for (int t = 0; t < T; t += 3) {
        STEP(0, 2, t);
        STEP(1, 0, t + 1);
        STEP(2, 1, t + 2);
    }
#undef STEP
#undef COMPUTE
#undef LOAD_TILE

    // -------- epilogue: bias (+gelu) (+residual), fp32 or bf16 out --------
#pragma unroll
    for (int mt = 0; mt < 2; mt++) {
        int row0 = m0 + wm0 + mt * 16 + g;
#pragma unroll
        for (int nt = 0; nt < 4; nt++) {
            int col = n0 + wn0 + nt * 8 + cq * 2;
            if (col < N) {
                float b0 = bias[col], b1 = bias[col + 1];
#pragma unroll
                for (int hh = 0; hh < 2; hh++) {
                    int row = row0 + 8 * hh;
                    float v0 = acc[mt][nt][hh * 2 + 0] + b0;
                    float v1 = acc[mt][nt][hh * 2 + 1] + b1;
                    if (act) { v0 = gelu_f(v0); v1 = gelu_f(v1); }
                    if (res) {
                        float2 rr = *(const float2*)&res[(size_t)row * ldc + col];
                        v0 += rr.x; v1 += rr.y;
                    }
                    if (out_bf16) {
                        *(__nv_bfloat162*)&((__nv_bfloat16*)Cc)[(size_t)row * ldc + col] =
                            __float22bfloat162_rn(make_float2(v0, v1));
                    } else {
                        *(float2*)&((float*)Cc)[(size_t)row * ldc + col] =
                            make_float2(v0, v1);
                    }
                }
            }
        }
    }
}

// ---------------------------------------------------------------------------
// Windowed PSA attention.  One block per 8x8 window (2048 windows).
// 384 threads = 64 q-tokens x 6 heads; softmax over 16 kv in registers.
// ---------------------------------------------------------------------------
__global__ __launch_bounds__(384) void attn_kernel(
    const __nv_bfloat16* __restrict__ qkv,
    const float* __restrict__ bias_table,
    __nv_bfloat16* __restrict__ aw)
{
    __shared__ float ks[16][192];
    __shared__ float vs[16][192];
    __shared__ float bt[296];
    int w  = blockIdx.x;
    int b  = w >> 10;
    int wi = w & 1023;
    int wy = wi >> 5, wx = wi & 31;
    int gbase = b*65536 + wy*2048 + wx*8;
    int tid = threadIdx.x;

    for (int i = tid; i < 294; i += 384) bt[i] = bias_table[i];
    {
        int kt = tid / 24;
        int f0 = (tid - kt * 24) * 8;
        int s0 = f0 / 96;
        int s1 = (f0 / 48) & 1;
        int c  = f0 % 48;
        int p0 = kt >> 2, p1 = kt & 3;
        int g  = gbase + (p0*2 + s0)*256 + (p1*2 + s1);
        const __nv_bfloat16* row = qkv + (size_t)g*QKVLD + 192;
        uint4 kraw = *(const uint4*)(row + c);
        uint4 vraw = *(const uint4*)(row + 48 + c);
        const __nv_bfloat162* kp = (const __nv_bfloat162*)&kraw;
        const __nv_bfloat162* vp = (const __nv_bfloat162*)&vraw;
        float2 t0 = __bfloat1622float2(kp[0]), t1 = __bfloat1622float2(kp[1]);
        float2 t2 = __bfloat1622float2(kp[2]), t3 = __bfloat1622float2(kp[3]);
        *(float4*)&ks[kt][f0]     = make_float4(t0.x, t0.y, t1.x, t1.y);
        *(float4*)&ks[kt][f0 + 4] = make_float4(t2.x, t2.y, t3.x, t3.y);
        t0 = __bfloat1622float2(vp[0]); t1 = __bfloat1622float2(vp[1]);
        t2 = __bfloat1622float2(vp[2]); t3 = __bfloat1622float2(vp[3]);
        *(float4*)&vs[kt][f0]     = make_float4(t0.x, t0.y, t1.x, t1.y);
        *(float4*)&vs[kt][f0 + 4] = make_float4(t2.x, t2.y, t3.x, t3.y);
    }
    __syncthreads();

    int h  = tid / 64;
    int qt = tid - h*64;
    int qi = qt >> 3, qj = qt & 7;
    int g  = gbase + qi*256 + qj;
    const __nv_bfloat16* qp = qkv + (size_t)g*QKVLD + h*32;
    float4 q4[8];
#pragma unroll
    for (int d = 0; d < 4; d++) {
        uint4 raw = *(const uint4*)(qp + d*8);
        const __nv_bfloat162* p2 = (const __nv_bfloat162*)&raw;
        float2 a0 = __bfloat1622float2(p2[0]);
        float2 a1 = __bfloat1622float2(p2[1]);
        float2 a2 = __bfloat1622float2(p2[2]);
        float2 a3 = __bfloat1622float2(p2[3]);
        q4[d*2]   = make_float4(a0.x*ATT_SCALE, a0.y*ATT_SCALE,
                                a1.x*ATT_SCALE, a1.y*ATT_SCALE);
        q4[d*2+1] = make_float4(a2.x*ATT_SCALE, a2.y*ATT_SCALE,
                                a3.x*ATT_SCALE, a3.y*ATT_SCALE);
    }
    float sc[16]; float mx = -1e30f;
    int rq0 = (qi >> 1) + 3, rq1 = (qj >> 1) + 3;
#pragma unroll
    for (int kt = 0; kt < 16; kt++) {
        const float4* kr = (const float4*)&ks[kt][h*32];
        float s = 0.f;
#pragma unroll
        for (int j = 0; j < 8; j++) {
            float4 kv4 = kr[j];
            s += q4[j].x*kv4.x + q4[j].y*kv4.y + q4[j].z*kv4.z + q4[j].w*kv4.w;
        }
        int rel = (rq0 - (kt >> 2))*7 + rq1 - (kt & 3);
        s += bt[rel*6 + h];
        sc[kt] = s;
        mx = fmaxf(mx, s);
    }
    float sum = 0.f;
#pragma unroll
    for (int kt = 0; kt < 16; kt++) { sc[kt] = __expf(sc[kt] - mx); sum += sc[kt]; }
    float inv = 1.f / sum;
    float4 o4[8];
#pragma unroll
    for (int j = 0; j < 8; j++) o4[j] = make_float4(0.f, 0.f, 0.f, 0.f);
#pragma unroll
    for (int kt = 0; kt < 16; kt++) {
        float a = sc[kt]*inv;
        const float4* vr = (const float4*)&vs[kt][h*32];
#pragma unroll
        for (int j = 0; j < 8; j++) {
            float4 vv = vr[j];
            o4[j].x += a*vv.x; o4[j].y += a*vv.y;
            o4[j].z += a*vv.z; o4[j].w += a*vv.w;
        }
    }
    __nv_bfloat16* op = aw + (size_t)g*192 + h*32;
#pragma unroll
    for (int j = 0; j < 4; j++) {
        uint4 o;
        __nv_bfloat162* o2 = (__nv_bfloat162*)&o;
        o2[0] = __float22bfloat162_rn(make_float2(o4[j*2].x,   o4[j*2].y));
        o2[1] = __float22bfloat162_rn(make_float2(o4[j*2].z,   o4[j*2].w));
        o2[2] = __float22bfloat162_rn(make_float2(o4[j*2+1].x, o4[j*2+1].y));
        o2[3] = __float22bfloat162_rn(make_float2(o4[j*2+1].z, o4[j*2+1].w));
        *(uint4*)(op + j*8) = o;
    }
}

// ---------------------------------------------------------------------------
// Depthwise 5x5 conv + GELU + residual:  out = h1 + gelu(conv(h1) + dwb)
// 4 x-adjacent tokens x 8 channels per thread: shared 5x8 column window
// (40 LDG.128) feeds all 4 tokens' taps (10 LDG/token). Packed __hfma2.
// ---------------------------------------------------------------------------
__global__ __launch_bounds__(256) void dwconv_kernel(
    const __nv_bfloat16* __restrict__ h1, const float* __restrict__ wk,
    const float* __restrict__ wb, __nv_bfloat16* __restrict__ out)
{
    __shared__ __align__(16) uint32_t ws2[25][64];  // bf16x2 per channel pair
    __shared__ float bs[128];
    int cb  = blockIdx.y * 128;
    int tid = threadIdx.x;
    for (int i = tid; i < 1600; i += 256) {
        int k = i >> 6, pp = i & 63;
        __nv_bfloat162 pk = __floats2bfloat162_rn(
            wk[(size_t)(cb + 2*pp)     * 25 + k],
            wk[(size_t)(cb + 2*pp + 1) * 25 + k]);
        ws2[k][pp] = *reinterpret_cast<uint32_t*>(&pk);
    }
    if (tid < 128) bs[tid] = wb[cb + tid];
    __syncthreads();

    int grp = tid >> 4;                   // quad index (0..15)
    int oc  = tid & 15;                   // channel octet
    int token0 = blockIdx.x * 64 + grp * 4;
    int b = token0 >> 16;
    int p = token0 & 65535;
    int y = p >> 8, x0 = p & 255;         // tokens x0..x0+3, same row
    int ch = cb + oc * 8;
    const size_t rowbase = (size_t)(b * 65536 + y * 256);

    __nv_bfloat162 z = __float2bfloat162_rn(0.f);
    __nv_bfloat162 acc[4][4];
#pragma unroll
    for (int tk = 0; tk < 4; tk++)
#pragma unroll
        for (int j = 0; j < 4; j++) acc[tk][j] = z;
    uint4 cen[4];
#pragma unroll
    for (int tk = 0; tk < 4; tk++) cen[tk] = make_uint4(0u,0u,0u,0u);

#pragma unroll
    for (int dy = 0; dy < 5; dy++) {
        int yy = y + dy - 2;
        bool yok = (unsigned)yy < 256u;
        size_t rb = (size_t)(b * 65536 + yy * 256);
        uint4 col[8];
#pragma unroll
        for (int jx = 0; jx < 8; jx++) {
            int xc = x0 + jx - 2;
            uint4 v = make_uint4(0u, 0u, 0u, 0u);
            if (yok && (unsigned)xc < 256u)
                v = *(const uint4*)&h1[(rb + xc) * HID + ch];
            col[jx] = v;
        }
        if (dy == 2) {
#pragma unroll
            for (int tk = 0; tk < 4; tk++) cen[tk] = col[tk + 2];
        }
#pragma unroll
        for (int jx = 0; jx < 8; jx++) {
            const __nv_bfloat162* vp = reinterpret_cast<const __nv_bfloat162*>(&col[jx]);
#pragma unroll
            for (int tk = 0; tk < 4; tk++) {
                int tap = jx - tk;
                if (tap >= 0 && tap < 5) {
                    uint4 wv = *(const uint4*)&ws2[dy*5 + tap][oc*4];
                    const __nv_bfloat162* wp =
                        reinterpret_cast<const __nv_bfloat162*>(&wv);
#pragma unroll
                    for (int j = 0; j < 4; j++)
                        acc[tk][j] = __hfma2(vp[j], wp[j], acc[tk][j]);
                }
            }
        }
    }

#pragma unroll
    for (int tk = 0; tk < 4; tk++) {
        const __nv_bfloat162* cp = reinterpret_cast<const __nv_bfloat162*>(&cen[tk]);
        uint4 o;
        __nv_bfloat162* op2 = reinterpret_cast<__nv_bfloat162*>(&o);
#pragma unroll
        for (int j = 0; j < 4; j++) {
            float b0 = bs[oc*8 + 2*j], b1 = bs[oc*8 + 2*j + 1];
            float2 a = __bfloat1622float2(acc[tk][j]);
            float2 c = __bfloat1622float2(cp[j]);
            op2[j] = __float22bfloat162_rn(make_float2(c.x + gelu_f(a.x + b0),
                                                       c.y + gelu_f(a.y + b1)));
        }
        *(uint4*)&out[(rowbase + x0 + tk) * HID + ch] = o;
    }
}

// ---------------------------------------------------------------------------
// Launch sequence (graph-capturable: kernel launches only)
// ---------------------------------------------------------------------------
extern "C" void kernel_launch(void* const* d_in, const int* in_sizes, int n_in,
                              void* d_out, int out_size)
{
    const float* x    = (const float*)d_in[0];
    const float* g1   = (const float*)d_in[1];
    const float* be1  = (const float*)d_in[2];
    const float* wq   = (const float*)d_in[3];
    const float* bq   = (const float*)d_in[4];
    const float* wkv  = (const float*)d_in[5];
    const float* bkv  = (const float*)d_in[6];
    const float* btab = (const float*)d_in[7];
    const float* wproj= (const float*)d_in[8];
    const float* bproj= (const float*)d_in[9];
    const float* g2   = (const float*)d_in[10];
    const float* be2  = (const float*)d_in[11];
    const float* w1f  = (const float*)d_in[12];
    const float* b1f  = (const float*)d_in[13];
    const float* dwk  = (const float*)d_in[14];
    const float* dwb  = (const float*)d_in[15];
    const float* w2f  = (const float*)d_in[16];
    const float* b2f  = (const float*)d_in[17];
    float* out = (float*)d_out;

    __nv_bfloat16 *xn, *qkvb, *aw, *h1, *h, *wb;
    float *x2, *bqkv;
    cudaGetSymbolAddress((void**)&xn,   g_xn);
    cudaGetSymbolAddress((void**)&qkvb, g_qkvb);
    cudaGetSymbolAddress((void**)&aw,   g_aw);
    cudaGetSymbolAddress((void**)&x2,   g_x2);
    cudaGetSymbolAddress((void**)&h1,   g_h1);
    cudaGetSymbolAddress((void**)&h,    g_h);
    cudaGetSymbolAddress((void**)&wb,   g_wb);
    cudaGetSymbolAddress((void**)&bqkv, g_bqkv);

    // 0. Weight/bias prep (bf16, QKV concat)
    prep_kernel<<<(387072 + 255)/256, 256>>>(wq, wkv, wproj, w1f, w2f, wb,
                                             bq, bkv, bqkv);

    // 1. LN1 -> xn (bf16)
    ln_kernel<<<NTOK/8, 256>>>(x, g1, be1, xn);
    // 2. QKV = xn @ wqkv + bqkv  (bf16, ldc=288; 5 n-blocks)
    gemm_bf16_kernel<<<dim3(5, NTOK/64), 128>>>(xn, 192, wb + WB_WQKV, 288, bqkv,
                                                qkvb, QKVLD, 288, 192,
                                                nullptr, 0, 1);
    // 3. Window attention -> aw (bf16, token order)
    attn_kernel<<<2048, 384>>>(qkvb, btab, aw);
    // 4. x2 = aw @ wproj + bproj + x  (fp32)
    gemm_bf16_kernel<<<dim3(3, NTOK/64), 128>>>(aw, 192, wb + WB_WPROJ, 192, bproj,
                                                x2, 192, 192, 192,
                                                x, 0, 0);
    // 5. LN2 -> xn (bf16)
    ln_kernel<<<NTOK/8, 256>>>(x2, g2, be2, xn);
    // 6. h1 = gelu(xn @ w1f + b1f)  (bf16)
    gemm_bf16_kernel<<<dim3(12, NTOK/64), 128>>>(xn, 192, wb + WB_W1F, HID, b1f,
                                                 h1, HID, HID, 192,
                                                 nullptr, 1, 1);
    // 7. h = h1 + gelu(dwconv(h1) + dwb)  (bf16, 4 tokens/thread)
    dwconv_kernel<<<dim3(NTOK/64, 6), 256>>>(h1, dwk, dwb, h);
    // 8. out = h @ w2f + b2f + x2  (fp32)
    gemm_bf16_kernel<<<dim3(3, NTOK/64), 128>>>(h, HID, wb + WB_W2F, 192, b2f,
                                                out, 192, 192, HID,
                                                x2, 0, 0);
}